// round 8
// baseline (speedup 1.0000x reference)
#include <cuda_runtime.h>
#include <cstdint>

// Problem constants
#define CDIM   256
#define HEADS  8
#define HD     32
#define SDIM   40          // H == W == D == 40
#define PDIM   64000       // H*W*D
#define BATCH  2

// GEMM tiling: 64x64 CTA tile, 128 threads (4 warps of 32x32), BK=16
#define BM 64
#define BN 64
#define BK 16
#define XPAD 8             // X row stride 72; 72 % 32 == 8 -> conflict-free frag gathers
#define KPAD 4             // W row stride 20; (g*20+t) mod 32 all distinct -> conflict-free

// Scratch (device globals; no allocation)
__device__ float g_q[BATCH * CDIM * PDIM];
__device__ float g_k[BATCH * CDIM * PDIM];
__device__ float g_v[BATCH * CDIM * PDIM];
__device__ float g_attn[BATCH * CDIM * PDIM];

__device__ __forceinline__ uint32_t to_tf32(float x) {
    uint32_t r;
    asm("cvt.rna.tf32.f32 %0, %1;" : "=r"(r) : "f"(x));
    return r;
}

__device__ __forceinline__ void mma_tf32(float* d, const uint32_t* a, const uint32_t* b) {
    asm volatile(
        "mma.sync.aligned.m16n8k8.row.col.f32.tf32.tf32.f32 "
        "{%0,%1,%2,%3}, {%4,%5,%6,%7}, {%8,%9}, {%0,%1,%2,%3};"
        : "+f"(d[0]), "+f"(d[1]), "+f"(d[2]), "+f"(d[3])
        : "r"(a[0]), "r"(a[1]), "r"(a[2]), "r"(a[3]), "r"(b[0]), "r"(b[1]));
}

__device__ __forceinline__ void cp16(void* smem, const void* gmem) {
    uint32_t sa = (uint32_t)__cvta_generic_to_shared(smem);
    asm volatile("cp.async.ca.shared.global [%0], [%1], 16;" :: "r"(sa), "l"(gmem));
}
__device__ __forceinline__ void cp_commit() { asm volatile("cp.async.commit_group;"); }
template <int N>
__device__ __forceinline__ void cp_wait() { asm volatile("cp.async.wait_group %0;" :: "n"(N)); }

// ---------------------------------------------------------------------------
// Kernel 1: fused QKV 1x1x1 conv, TF32 MMA, cp.async double-buffered.
// 128 threads, 64x64 tile -> 3 CTAs/SM (12 warps) for latency hiding.
// ---------------------------------------------------------------------------
__global__ __launch_bounds__(128, 3) void qkv_gemm(
    const float* __restrict__ x,
    const float* __restrict__ wq, const float* __restrict__ bq,
    const float* __restrict__ wk, const float* __restrict__ bk,
    const float* __restrict__ wv, const float* __restrict__ bv)
{
    __shared__ __align__(16) float sX [2][BK][BN + XPAD];   // [k][n] stride 72
    __shared__ __align__(16) float sWq[2][BM][BK + KPAD];   // [m][k] stride 20
    __shared__ __align__(16) float sWk[2][BM][BK + KPAD];
    __shared__ __align__(16) float sWv[2][BM][BK + KPAD];

    const int b    = blockIdx.z;
    const int m0   = blockIdx.y * BM;
    const int n0   = blockIdx.x * BN;
    const int tid  = threadIdx.x;
    const int warp = tid >> 5;           // 0..3
    const int lane = tid & 31;
    const int wm   = warp >> 1;          // 0..1
    const int wn   = warp & 1;           // 0..1
    const int g    = lane >> 2;          // 0..7
    const int t    = lane & 3;           // 0..3

    const float* xb = x + (size_t)b * CDIM * PDIM;

    // loader indices
    const int xl_kr0 = tid >> 4;               // 0..7 (i=0), +8 (i=1)
    const int xl_nc  = (tid & 15) * 4;
    const int wl_m   = tid & 63;               // 0..63
    const int wl_k4  = (tid >> 6) << 2;        // 0,4 (second cp at +8)

    float accq[2][4][4] = {};
    float acck[2][4][4] = {};
    float accv[2][4][4] = {};

    // ---- prologue: stage 0
    {
        cp16(&sX[0][xl_kr0    ][xl_nc], &xb[(size_t)(xl_kr0    ) * PDIM + n0 + xl_nc]);
        cp16(&sX[0][xl_kr0 + 8][xl_nc], &xb[(size_t)(xl_kr0 + 8) * PDIM + n0 + xl_nc]);
        const size_t widx = (size_t)(m0 + wl_m) * CDIM + wl_k4;
        cp16(&sWq[0][wl_m][wl_k4    ], &wq[widx    ]);
        cp16(&sWq[0][wl_m][wl_k4 + 8], &wq[widx + 8]);
        cp16(&sWk[0][wl_m][wl_k4    ], &wk[widx    ]);
        cp16(&sWk[0][wl_m][wl_k4 + 8], &wk[widx + 8]);
        cp16(&sWv[0][wl_m][wl_k4    ], &wv[widx    ]);
        cp16(&sWv[0][wl_m][wl_k4 + 8], &wv[widx + 8]);
        cp_commit();
    }

    const int NT = CDIM / BK;   // 16
    for (int it = 0; it < NT; it++) {
        const int st = it & 1;
        if (it + 1 < NT) {
            const int ns = st ^ 1;
            const int k0 = (it + 1) * BK;
            cp16(&sX[ns][xl_kr0    ][xl_nc], &xb[(size_t)(k0 + xl_kr0    ) * PDIM + n0 + xl_nc]);
            cp16(&sX[ns][xl_kr0 + 8][xl_nc], &xb[(size_t)(k0 + xl_kr0 + 8) * PDIM + n0 + xl_nc]);
            const size_t widx = (size_t)(m0 + wl_m) * CDIM + k0 + wl_k4;
            cp16(&sWq[ns][wl_m][wl_k4    ], &wq[widx    ]);
            cp16(&sWq[ns][wl_m][wl_k4 + 8], &wq[widx + 8]);
            cp16(&sWk[ns][wl_m][wl_k4    ], &wk[widx    ]);
            cp16(&sWk[ns][wl_m][wl_k4 + 8], &wk[widx + 8]);
            cp16(&sWv[ns][wl_m][wl_k4    ], &wv[widx    ]);
            cp16(&sWv[ns][wl_m][wl_k4 + 8], &wv[widx + 8]);
            cp_commit();
            cp_wait<1>();
        } else {
            cp_wait<0>();
        }
        __syncthreads();

        const float (*X)[BN + XPAD] = sX[st];
        const float (*Wq)[BK + KPAD] = sWq[st];
        const float (*Wk)[BK + KPAD] = sWk[st];
        const float (*Wv)[BK + KPAD] = sWv[st];

        #pragma unroll
        for (int ks = 0; ks < BK; ks += 8) {
            uint32_t bf[4][2];
            #pragma unroll
            for (int ni = 0; ni < 4; ni++) {
                int ncol = wn * 32 + ni * 8 + g;
                bf[ni][0] = to_tf32(X[ks + t    ][ncol]);
                bf[ni][1] = to_tf32(X[ks + t + 4][ncol]);
            }
            #pragma unroll
            for (int mat = 0; mat < 3; mat++) {
                const float (*W)[BK + KPAD] = (mat == 0) ? Wq : (mat == 1) ? Wk : Wv;
                float (*acc)[4][4]          = (mat == 0) ? accq : (mat == 1) ? acck : accv;
                #pragma unroll
                for (int mi = 0; mi < 2; mi++) {
                    int r = wm * 32 + mi * 16 + g;
                    uint32_t af[4];
                    af[0] = to_tf32(W[r    ][ks + t    ]);
                    af[1] = to_tf32(W[r + 8][ks + t    ]);
                    af[2] = to_tf32(W[r    ][ks + t + 4]);
                    af[3] = to_tf32(W[r + 8][ks + t + 4]);
                    #pragma unroll
                    for (int ni = 0; ni < 4; ni++)
                        mma_tf32(acc[mi][ni], af, bf[ni]);
                }
            }
        }
        __syncthreads();
    }

    // Epilogue: bias + store
    #pragma unroll
    for (int mi = 0; mi < 2; mi++) {
        #pragma unroll
        for (int rr = 0; rr < 2; rr++) {
            const int m  = m0 + wm * 32 + mi * 16 + g + rr * 8;
            const float biq = bq[m], bik = bk[m], biv = bv[m];
            const size_t rowbase = ((size_t)b * CDIM + m) * PDIM;
            #pragma unroll
            for (int ni = 0; ni < 4; ni++) {
                const size_t o = rowbase + n0 + wn * 32 + ni * 8 + t * 2;
                float2 vq = {accq[mi][ni][rr * 2] + biq, accq[mi][ni][rr * 2 + 1] + biq};
                float2 vk = {acck[mi][ni][rr * 2] + bik, acck[mi][ni][rr * 2 + 1] + bik};
                float2 vv = {accv[mi][ni][rr * 2] + biv, accv[mi][ni][rr * 2 + 1] + biv};
                *(float2*)&g_q[o] = vq;
                *(float2*)&g_k[o] = vk;
                *(float2*)&g_v[o] = vv;
            }
        }
    }
}

// ---------------------------------------------------------------------------
// Kernel 2: attention (the three reference branches are bitwise-identical
// reshapes since H==W==D -> compute one, scale by 3).
// 2 channels per block; S overlays the dead Q tile.
// ---------------------------------------------------------------------------
__global__ __launch_bounds__(256) void attn_kernel()
{
    __shared__ float sQ[2][40][41];   // Q, later S
    __shared__ float sK[2][40][41];
    __shared__ float sV[2][40][41];

    const int s1    = blockIdx.x;       // 0..39
    const int cpair = blockIdx.y;       // 0..15
    const int bh    = blockIdx.z;       // 0..15
    const int tid   = threadIdx.x;
    const int half  = tid >> 7;         // 0/1 -> channel within pair
    const int t2    = tid & 127;

    const int c = cpair * 2 + half;
    const size_t base = (size_t)(bh * HD + c) * PDIM + s1 * 1600;

    for (int e = t2; e < 1600; e += 128) {
        int r  = e / 40;
        int cc = e - r * 40;
        sQ[half][r][cc] = g_q[base + e];
        sK[half][r][cc] = g_k[base + e];
        sV[half][r][cc] = g_v[base + e];
    }
    __syncthreads();

    const float scale = 0.17677669529663687f;   // 32^-0.5
    const int i0 = (t2 / 10) * 4;
    const int j0 = (t2 % 10) * 4;

    // S = Q K^T * scale (into registers first; Q still being read by peers)
    float acc[4][4] = {};
    if (t2 < 100) {
        #pragma unroll 8
        for (int k = 0; k < 40; k++) {
            float qv[4], kv[4];
            #pragma unroll
            for (int a = 0; a < 4; a++) { qv[a] = sQ[half][i0 + a][k]; kv[a] = sK[half][j0 + a][k]; }
            #pragma unroll
            for (int a = 0; a < 4; a++)
                #pragma unroll
                for (int bb = 0; bb < 4; bb++)
                    acc[a][bb] = fmaf(qv[a], kv[bb], acc[a][bb]);
        }
    }
    __syncthreads();
    if (t2 < 100) {
        #pragma unroll
        for (int a = 0; a < 4; a++)
            #pragma unroll
            for (int bb = 0; bb < 4; bb++)
                sQ[half][i0 + a][j0 + bb] = acc[a][bb] * scale;   // S overwrites Q
    }
    __syncthreads();

    // row softmax
    if (t2 < 40) {
        float mx = -1e30f;
        #pragma unroll 8
        for (int j = 0; j < 40; j++) mx = fmaxf(mx, sQ[half][t2][j]);
        float sum = 0.0f;
        #pragma unroll 8
        for (int j = 0; j < 40; j++) {
            float ev = __expf(sQ[half][t2][j] - mx);
            sQ[half][t2][j] = ev;
            sum += ev;
        }
        const float inv = 1.0f / sum;
        #pragma unroll 8
        for (int j = 0; j < 40; j++) sQ[half][t2][j] *= inv;
    }
    __syncthreads();

    // O = 3 * (S V)
    if (t2 < 100) {
        float acc2[4][4] = {};
        #pragma unroll 8
        for (int k = 0; k < 40; k++) {
            float av[4], vv[4];
            #pragma unroll
            for (int a = 0; a < 4; a++) { av[a] = sQ[half][i0 + a][k]; vv[a] = sV[half][k][j0 + a]; }
            #pragma unroll
            for (int a = 0; a < 4; a++)
                #pragma unroll
                for (int bb = 0; bb < 4; bb++)
                    acc2[a][bb] = fmaf(av[a], vv[bb], acc2[a][bb]);
        }
        #pragma unroll
        for (int a = 0; a < 4; a++) {
            float4 o = {3.0f * acc2[a][0], 3.0f * acc2[a][1],
                        3.0f * acc2[a][2], 3.0f * acc2[a][3]};
            *(float4*)&g_attn[base + (size_t)(i0 + a) * 40 + j0] = o;
        }
    }
}

// ---------------------------------------------------------------------------
// Kernel 3: output projection, TF32 MMA + cp.async double buffer.
// 128 threads, 64x64 tile.
// ---------------------------------------------------------------------------
__global__ __launch_bounds__(128, 3) void proj_gemm(
    const float* __restrict__ wp, const float* __restrict__ bp,
    float* __restrict__ out)
{
    __shared__ __align__(16) float sX[2][BK][BN + XPAD];
    __shared__ __align__(16) float sW[2][BM][BK + KPAD];

    const int b    = blockIdx.z;
    const int m0   = blockIdx.y * BM;
    const int n0   = blockIdx.x * BN;
    const int tid  = threadIdx.x;
    const int warp = tid >> 5;
    const int lane = tid & 31;
    const int wm   = warp >> 1;
    const int wn   = warp & 1;
    const int g    = lane >> 2;
    const int t    = lane & 3;

    const float* xb = g_attn + (size_t)b * CDIM * PDIM;

    const int xl_kr0 = tid >> 4;
    const int xl_nc  = (tid & 15) * 4;
    const int wl_m   = tid & 63;
    const int wl_k4  = (tid >> 6) << 2;

    float acc[2][4][4] = {};

    {
        cp16(&sX[0][xl_kr0    ][xl_nc], &xb[(size_t)(xl_kr0    ) * PDIM + n0 + xl_nc]);
        cp16(&sX[0][xl_kr0 + 8][xl_nc], &xb[(size_t)(xl_kr0 + 8) * PDIM + n0 + xl_nc]);
        const size_t widx = (size_t)(m0 + wl_m) * CDIM + wl_k4;
        cp16(&sW[0][wl_m][wl_k4    ], &wp[widx    ]);
        cp16(&sW[0][wl_m][wl_k4 + 8], &wp[widx + 8]);
        cp_commit();
    }

    const int NT = CDIM / BK;
    for (int it = 0; it < NT; it++) {
        const int st = it & 1;
        if (it + 1 < NT) {
            const int ns = st ^ 1;
            const int k0 = (it + 1) * BK;
            cp16(&sX[ns][xl_kr0    ][xl_nc], &xb[(size_t)(k0 + xl_kr0    ) * PDIM + n0 + xl_nc]);
            cp16(&sX[ns][xl_kr0 + 8][xl_nc], &xb[(size_t)(k0 + xl_kr0 + 8) * PDIM + n0 + xl_nc]);
            const size_t widx = (size_t)(m0 + wl_m) * CDIM + k0 + wl_k4;
            cp16(&sW[ns][wl_m][wl_k4    ], &wp[widx    ]);
            cp16(&sW[ns][wl_m][wl_k4 + 8], &wp[widx + 8]);
            cp_commit();
            cp_wait<1>();
        } else {
            cp_wait<0>();
        }
        __syncthreads();

        const float (*X)[BN + XPAD] = sX[st];
        const float (*W)[BK + KPAD] = sW[st];

        #pragma unroll
        for (int ks = 0; ks < BK; ks += 8) {
            uint32_t bf[4][2];
            #pragma unroll
            for (int ni = 0; ni < 4; ni++) {
                int ncol = wn * 32 + ni * 8 + g;
                bf[ni][0] = to_tf32(X[ks + t    ][ncol]);
                bf[ni][1] = to_tf32(X[ks + t + 4][ncol]);
            }
            #pragma unroll
            for (int mi = 0; mi < 2; mi++) {
                int r = wm * 32 + mi * 16 + g;
                uint32_t af[4];
                af[0] = to_tf32(W[r    ][ks + t    ]);
                af[1] = to_tf32(W[r + 8][ks + t    ]);
                af[2] = to_tf32(W[r    ][ks + t + 4]);
                af[3] = to_tf32(W[r + 8][ks + t + 4]);
                #pragma unroll
                for (int ni = 0; ni < 4; ni++)
                    mma_tf32(acc[mi][ni], af, bf[ni]);
            }
        }
        __syncthreads();
    }

    #pragma unroll
    for (int mi = 0; mi < 2; mi++) {
        #pragma unroll
        for (int rr = 0; rr < 2; rr++) {
            const int m  = m0 + wm * 32 + mi * 16 + g + rr * 8;
            const float bi = bp[m];
            const size_t rowbase = ((size_t)b * CDIM + m) * PDIM;
            #pragma unroll
            for (int ni = 0; ni < 4; ni++) {
                const size_t o = rowbase + n0 + wn * 32 + ni * 8 + t * 2;
                float2 v = {acc[mi][ni][rr * 2] + bi, acc[mi][ni][rr * 2 + 1] + bi};
                *(float2*)&out[o] = v;
            }
        }
    }
}

// ---------------------------------------------------------------------------
extern "C" void kernel_launch(void* const* d_in, const int* in_sizes, int n_in,
                              void* d_out, int out_size)
{
    const float* x  = (const float*)d_in[0];
    const float* wq = (const float*)d_in[1];
    const float* bq = (const float*)d_in[2];
    const float* wk = (const float*)d_in[3];
    const float* bk = (const float*)d_in[4];
    const float* wv = (const float*)d_in[5];
    const float* bv = (const float*)d_in[6];
    const float* wp = (const float*)d_in[7];
    const float* bp = (const float*)d_in[8];
    float* out = (float*)d_out;

    dim3 gemm_grid(PDIM / BN, CDIM / BM, BATCH);     // 1000 x 4 x 2
    qkv_gemm<<<gemm_grid, 128>>>(x, wq, bq, wk, bk, wv, bv);

    dim3 attn_grid(SDIM, HD / 2, BATCH * HEADS);     // 40 x 16 x 16
    attn_kernel<<<attn_grid, 256>>>();

    proj_gemm<<<gemm_grid, 128>>>(wp, bp, out);
}

// round 11
// speedup vs baseline: 1.1893x; 1.1893x over previous
#include <cuda_runtime.h>
#include <cstdint>

// Problem constants
#define CDIM   256
#define HEADS  8
#define HD     32
#define SDIM   40          // H == W == D == 40
#define PDIM   64000       // H*W*D
#define BATCH  2

// GEMM tiling (R7 shape: 256 threads, 64x128 tile, BK=16)
#define BM 64
#define BN 128
#define BK 16
#define XPAD 8             // X row stride 136; 136 % 32 == 8 -> conflict-free frag gathers
#define KPAD 4             // W row stride 20; (g*20+t) mod 32 all distinct -> conflict-free

#define WELEMS (CDIM * CDIM)        // 65536 per weight matrix
#define XELEMS (BATCH * CDIM * PDIM)

// Scratch (device globals; no allocation). Footprint matches proven R5/R7 + 1MB.
__device__ float g_q   [XELEMS];
__device__ float g_k   [XELEMS];
__device__ float g_v   [XELEMS];
__device__ float g_attn[XELEMS];
__device__ float g_wc  [4 * WELEMS];    // wq,wk,wv,wp pre-rounded to tf32

__device__ __forceinline__ uint32_t to_tf32(float x) {
    uint32_t r;
    asm("cvt.rna.tf32.f32 %0, %1;" : "=r"(r) : "f"(x));
    return r;
}
__device__ __forceinline__ float to_tf32f(float x) {
    return __uint_as_float(to_tf32(x));
}

__device__ __forceinline__ void mma_tf32(float* d, const uint32_t* a, const uint32_t* b) {
    asm volatile(
        "mma.sync.aligned.m16n8k8.row.col.f32.tf32.tf32.f32 "
        "{%0,%1,%2,%3}, {%4,%5,%6,%7}, {%8,%9}, {%0,%1,%2,%3};"
        : "+f"(d[0]), "+f"(d[1]), "+f"(d[2]), "+f"(d[3])
        : "r"(a[0]), "r"(a[1]), "r"(a[2]), "r"(a[3]), "r"(b[0]), "r"(b[1]));
}

__device__ __forceinline__ void cp16(void* smem, const void* gmem) {
    uint32_t sa = (uint32_t)__cvta_generic_to_shared(smem);
    asm volatile("cp.async.ca.shared.global [%0], [%1], 16;" :: "r"(sa), "l"(gmem));
}
__device__ __forceinline__ void cp_commit() { asm volatile("cp.async.commit_group;"); }
template <int N>
__device__ __forceinline__ void cp_wait() { asm volatile("cp.async.wait_group %0;" :: "n"(N)); }

// ---------------------------------------------------------------------------
// Kernel 0: one-time TF32 rounding of the four weight matrices (1MB total).
// ---------------------------------------------------------------------------
__global__ __launch_bounds__(256) void convert_w(
    const float* __restrict__ wq, const float* __restrict__ wk,
    const float* __restrict__ wv, const float* __restrict__ wp)
{
    const int stride = gridDim.x * blockDim.x;
    const int nw4 = WELEMS / 4;      // 16384 float4 per matrix
    for (int i = blockIdx.x * blockDim.x + threadIdx.x; i < nw4; i += stride) {
        float4 a = ((const float4*)wq)[i];
        float4 b = ((const float4*)wk)[i];
        float4 c = ((const float4*)wv)[i];
        float4 d = ((const float4*)wp)[i];
        ((float4*)g_wc)[i          ] = {to_tf32f(a.x), to_tf32f(a.y), to_tf32f(a.z), to_tf32f(a.w)};
        ((float4*)g_wc)[i +     nw4] = {to_tf32f(b.x), to_tf32f(b.y), to_tf32f(b.z), to_tf32f(b.w)};
        ((float4*)g_wc)[i + 2 * nw4] = {to_tf32f(c.x), to_tf32f(c.y), to_tf32f(c.z), to_tf32f(c.w)};
        ((float4*)g_wc)[i + 3 * nw4] = {to_tf32f(d.x), to_tf32f(d.y), to_tf32f(d.z), to_tf32f(d.w)};
    }
}

// ---------------------------------------------------------------------------
// Kernel 1: fused QKV 1x1x1 conv, TF32 MMA, cp.async double-buffered.
// Weights pre-rounded (no W CVTs); X converted at fragment build (8 CVT/step).
// ---------------------------------------------------------------------------
__global__ __launch_bounds__(256, 2) void qkv_gemm(
    const float* __restrict__ x,
    const float* __restrict__ bq, const float* __restrict__ bk,
    const float* __restrict__ bv)
{
    __shared__ __align__(16) float    sX [2][BK][BN + XPAD];   // [k][n]
    __shared__ __align__(16) uint32_t sWq[2][BM][BK + KPAD];   // [m][k], pre-rounded bits
    __shared__ __align__(16) uint32_t sWk[2][BM][BK + KPAD];
    __shared__ __align__(16) uint32_t sWv[2][BM][BK + KPAD];

    const int b    = blockIdx.z;
    const int m0   = blockIdx.y * BM;
    const int n0   = blockIdx.x * BN;
    const int tid  = threadIdx.x;
    const int warp = tid >> 5;
    const int lane = tid & 31;
    const int wm   = warp >> 2;          // 0..1
    const int wn   = warp & 3;           // 0..3
    const int g    = lane >> 2;          // 0..7
    const int t    = lane & 3;           // 0..3

    const float* xb = x + (size_t)b * CDIM * PDIM;
    const float* wq = g_wc;
    const float* wk = g_wc + WELEMS;
    const float* wv = g_wc + 2 * WELEMS;

    // loader indices
    const int xl_kr0 = tid >> 5;               // 0..7 (+8 for second)
    const int xl_nc  = (tid & 31) * 4;
    const int wl_m   = tid & 63;               // 0..63
    const int wl_k4  = (tid >> 6) << 2;        // 0,4,8,12

    float accq[2][4][4] = {};
    float acck[2][4][4] = {};
    float accv[2][4][4] = {};

    // ---- prologue: stage 0
    {
        cp16(&sX[0][xl_kr0    ][xl_nc], &xb[(size_t)(xl_kr0    ) * PDIM + n0 + xl_nc]);
        cp16(&sX[0][xl_kr0 + 8][xl_nc], &xb[(size_t)(xl_kr0 + 8) * PDIM + n0 + xl_nc]);
        const size_t widx = (size_t)(m0 + wl_m) * CDIM + wl_k4;
        cp16(&sWq[0][wl_m][wl_k4], &wq[widx]);
        cp16(&sWk[0][wl_m][wl_k4], &wk[widx]);
        cp16(&sWv[0][wl_m][wl_k4], &wv[widx]);
        cp_commit();
    }

    const int NT = CDIM / BK;   // 16
    for (int it = 0; it < NT; it++) {
        const int st = it & 1;
        if (it + 1 < NT) {
            const int ns = st ^ 1;
            const int k0 = (it + 1) * BK;
            cp16(&sX[ns][xl_kr0    ][xl_nc], &xb[(size_t)(k0 + xl_kr0    ) * PDIM + n0 + xl_nc]);
            cp16(&sX[ns][xl_kr0 + 8][xl_nc], &xb[(size_t)(k0 + xl_kr0 + 8) * PDIM + n0 + xl_nc]);
            const size_t widx = (size_t)(m0 + wl_m) * CDIM + k0 + wl_k4;
            cp16(&sWq[ns][wl_m][wl_k4], &wq[widx]);
            cp16(&sWk[ns][wl_m][wl_k4], &wk[widx]);
            cp16(&sWv[ns][wl_m][wl_k4], &wv[widx]);
            cp_commit();
            cp_wait<1>();
        } else {
            cp_wait<0>();
        }
        __syncthreads();

        const float    (*X)[BN + XPAD]  = sX[st];
        const uint32_t (*Wq)[BK + KPAD] = sWq[st];
        const uint32_t (*Wk)[BK + KPAD] = sWk[st];
        const uint32_t (*Wv)[BK + KPAD] = sWv[st];

        #pragma unroll
        for (int ks = 0; ks < BK; ks += 8) {
            uint32_t bf[4][2];
            #pragma unroll
            for (int ni = 0; ni < 4; ni++) {
                int ncol = wn * 32 + ni * 8 + g;
                bf[ni][0] = to_tf32(X[ks + t    ][ncol]);
                bf[ni][1] = to_tf32(X[ks + t + 4][ncol]);
            }
            #pragma unroll
            for (int mat = 0; mat < 3; mat++) {
                const uint32_t (*W)[BK + KPAD] = (mat == 0) ? Wq : (mat == 1) ? Wk : Wv;
                float (*acc)[4][4]             = (mat == 0) ? accq : (mat == 1) ? acck : accv;
                #pragma unroll
                for (int mi = 0; mi < 2; mi++) {
                    int r = wm * 32 + mi * 16 + g;
                    uint32_t af[4];
                    af[0] = W[r    ][ks + t    ];
                    af[1] = W[r + 8][ks + t    ];
                    af[2] = W[r    ][ks + t + 4];
                    af[3] = W[r + 8][ks + t + 4];
                    #pragma unroll
                    for (int ni = 0; ni < 4; ni++)
                        mma_tf32(acc[mi][ni], af, bf[ni]);
                }
            }
        }
        __syncthreads();
    }

    // Epilogue: bias + store
    #pragma unroll
    for (int mi = 0; mi < 2; mi++) {
        #pragma unroll
        for (int rr = 0; rr < 2; rr++) {
            const int m  = m0 + wm * 32 + mi * 16 + g + rr * 8;
            const float biq = bq[m], bik = bk[m], biv = bv[m];
            const size_t rowbase = ((size_t)b * CDIM + m) * PDIM;
            #pragma unroll
            for (int ni = 0; ni < 4; ni++) {
                const size_t o = rowbase + n0 + wn * 32 + ni * 8 + t * 2;
                float2 vq = {accq[mi][ni][rr * 2] + biq, accq[mi][ni][rr * 2 + 1] + biq};
                float2 vk = {acck[mi][ni][rr * 2] + bik, acck[mi][ni][rr * 2 + 1] + bik};
                float2 vv = {accv[mi][ni][rr * 2] + biv, accv[mi][ni][rr * 2 + 1] + biv};
                *(float2*)&g_q[o] = vq;
                *(float2*)&g_k[o] = vk;
                *(float2*)&g_v[o] = vv;
            }
        }
    }
}

// ---------------------------------------------------------------------------
// Kernel 2: attention (the three reference branches are bitwise-identical
// reshapes since H==W==D -> compute one, scale by 3).
// 2 channels per block; S overlays the dead Q tile. Output stored pre-rounded
// to tf32 so proj_gemm needs no CVTs at all.
// ---------------------------------------------------------------------------
__global__ __launch_bounds__(256) void attn_kernel()
{
    __shared__ float sQ[2][40][41];   // Q, later S
    __shared__ float sK[2][40][41];
    __shared__ float sV[2][40][41];

    const int s1    = blockIdx.x;       // 0..39
    const int cpair = blockIdx.y;       // 0..15
    const int bh    = blockIdx.z;       // 0..15
    const int tid   = threadIdx.x;
    const int half  = tid >> 7;         // 0/1 -> channel within pair
    const int t2    = tid & 127;

    const int c = cpair * 2 + half;
    const size_t base = (size_t)(bh * HD + c) * PDIM + s1 * 1600;

    for (int e = t2; e < 1600; e += 128) {
        int r  = e / 40;
        int cc = e - r * 40;
        sQ[half][r][cc] = g_q[base + e];
        sK[half][r][cc] = g_k[base + e];
        sV[half][r][cc] = g_v[base + e];
    }
    __syncthreads();

    const float scale = 0.17677669529663687f;   // 32^-0.5
    const int i0 = (t2 / 10) * 4;
    const int j0 = (t2 % 10) * 4;

    // S = Q K^T * scale (registers first; Q still being read by peers)
    float acc[4][4] = {};
    if (t2 < 100) {
        #pragma unroll 8
        for (int k = 0; k < 40; k++) {
            float qv[4], kv[4];
            #pragma unroll
            for (int a = 0; a < 4; a++) { qv[a] = sQ[half][i0 + a][k]; kv[a] = sK[half][j0 + a][k]; }
            #pragma unroll
            for (int a = 0; a < 4; a++)
                #pragma unroll
                for (int bb = 0; bb < 4; bb++)
                    acc[a][bb] = fmaf(qv[a], kv[bb], acc[a][bb]);
        }
    }
    __syncthreads();
    if (t2 < 100) {
        #pragma unroll
        for (int a = 0; a < 4; a++)
            #pragma unroll
            for (int bb = 0; bb < 4; bb++)
                sQ[half][i0 + a][j0 + bb] = acc[a][bb] * scale;   // S overwrites Q
    }
    __syncthreads();

    // row softmax
    if (t2 < 40) {
        float mx = -1e30f;
        #pragma unroll 8
        for (int j = 0; j < 40; j++) mx = fmaxf(mx, sQ[half][t2][j]);
        float sum = 0.0f;
        #pragma unroll 8
        for (int j = 0; j < 40; j++) {
            float ev = __expf(sQ[half][t2][j] - mx);
            sQ[half][t2][j] = ev;
            sum += ev;
        }
        const float inv = 1.0f / sum;
        #pragma unroll 8
        for (int j = 0; j < 40; j++) sQ[half][t2][j] *= inv;
    }
    __syncthreads();

    // O = 3 * (S V), rounded to tf32 for proj
    if (t2 < 100) {
        float acc2[4][4] = {};
        #pragma unroll 8
        for (int k = 0; k < 40; k++) {
            float av[4], vv[4];
            #pragma unroll
            for (int a = 0; a < 4; a++) { av[a] = sQ[half][i0 + a][k]; vv[a] = sV[half][k][j0 + a]; }
            #pragma unroll
            for (int a = 0; a < 4; a++)
                #pragma unroll
                for (int bb = 0; bb < 4; bb++)
                    acc2[a][bb] = fmaf(av[a], vv[bb], acc2[a][bb]);
        }
        #pragma unroll
        for (int a = 0; a < 4; a++) {
            float4 o = {to_tf32f(3.0f * acc2[a][0]), to_tf32f(3.0f * acc2[a][1]),
                        to_tf32f(3.0f * acc2[a][2]), to_tf32f(3.0f * acc2[a][3])};
            *(float4*)&g_attn[base + (size_t)(i0 + a) * 40 + j0] = o;
        }
    }
}

// ---------------------------------------------------------------------------
// Kernel 3: output projection, TF32 MMA + cp.async double buffer, zero CVTs
// (X from g_attn is pre-rounded by attn_kernel; W pre-rounded by convert_w).
// ---------------------------------------------------------------------------
__global__ __launch_bounds__(256, 2) void proj_gemm(
    const float* __restrict__ bp, float* __restrict__ out)
{
    __shared__ __align__(16) uint32_t sX[2][BK][BN + XPAD];
    __shared__ __align__(16) uint32_t sW[2][BM][BK + KPAD];

    const int b    = blockIdx.z;
    const int m0   = blockIdx.y * BM;
    const int n0   = blockIdx.x * BN;
    const int tid  = threadIdx.x;
    const int warp = tid >> 5;
    const int lane = tid & 31;
    const int wm   = warp >> 2;
    const int wn   = warp & 3;
    const int g    = lane >> 2;
    const int t    = lane & 3;

    const float* xb = g_attn + (size_t)b * CDIM * PDIM;
    const float* wp = g_wc + 3 * WELEMS;

    const int xl_kr0 = tid >> 5;
    const int xl_nc  = (tid & 31) * 4;
    const int wl_m   = tid & 63;
    const int wl_k4  = (tid >> 6) << 2;

    float acc[2][4][4] = {};

    {
        cp16(&sX[0][xl_kr0    ][xl_nc], &xb[(size_t)(xl_kr0    ) * PDIM + n0 + xl_nc]);
        cp16(&sX[0][xl_kr0 + 8][xl_nc], &xb[(size_t)(xl_kr0 + 8) * PDIM + n0 + xl_nc]);
        cp16(&sW[0][wl_m][wl_k4], &wp[(size_t)(m0 + wl_m) * CDIM + wl_k4]);
        cp_commit();
    }

    const int NT = CDIM / BK;
    for (int it = 0; it < NT; it++) {
        const int st = it & 1;
        if (it + 1 < NT) {
            const int ns = st ^ 1;
            const int k0 = (it + 1) * BK;
            cp16(&sX[ns][xl_kr0    ][xl_nc], &xb[(size_t)(k0 + xl_kr0    ) * PDIM + n0 + xl_nc]);
            cp16(&sX[ns][xl_kr0 + 8][xl_nc], &xb[(size_t)(k0 + xl_kr0 + 8) * PDIM + n0 + xl_nc]);
            cp16(&sW[ns][wl_m][wl_k4], &wp[(size_t)(m0 + wl_m) * CDIM + k0 + wl_k4]);
            cp_commit();
            cp_wait<1>();
        } else {
            cp_wait<0>();
        }
        __syncthreads();

        const uint32_t (*X)[BN + XPAD] = sX[st];
        const uint32_t (*W)[BK + KPAD] = sW[st];

        #pragma unroll
        for (int ks = 0; ks < BK; ks += 8) {
            uint32_t bf[4][2];
            #pragma unroll
            for (int ni = 0; ni < 4; ni++) {
                int ncol = wn * 32 + ni * 8 + g;
                bf[ni][0] = X[ks + t    ][ncol];
                bf[ni][1] = X[ks + t + 4][ncol];
            }
            #pragma unroll
            for (int mi = 0; mi < 2; mi++) {
                int r = wm * 32 + mi * 16 + g;
                uint32_t af[4];
                af[0] = W[r    ][ks + t    ];
                af[1] = W[r + 8][ks + t    ];
                af[2] = W[r    ][ks + t + 4];
                af[3] = W[r + 8][ks + t + 4];
                #pragma unroll
                for (int ni = 0; ni < 4; ni++)
                    mma_tf32(acc[mi][ni], af, bf[ni]);
            }
        }
        __syncthreads();
    }

    #pragma unroll
    for (int mi = 0; mi < 2; mi++) {
        #pragma unroll
        for (int rr = 0; rr < 2; rr++) {
            const int m  = m0 + wm * 32 + mi * 16 + g + rr * 8;
            const float bi = bp[m];
            const size_t rowbase = ((size_t)b * CDIM + m) * PDIM;
            #pragma unroll
            for (int ni = 0; ni < 4; ni++) {
                const size_t o = rowbase + n0 + wn * 32 + ni * 8 + t * 2;
                float2 v = {acc[mi][ni][rr * 2] + bi, acc[mi][ni][rr * 2 + 1] + bi};
                *(float2*)&out[o] = v;
            }
        }
    }
}

// ---------------------------------------------------------------------------
extern "C" void kernel_launch(void* const* d_in, const int* in_sizes, int n_in,
                              void* d_out, int out_size)
{
    const float* x  = (const float*)d_in[0];
    const float* wq = (const float*)d_in[1];
    const float* bq = (const float*)d_in[2];
    const float* wk = (const float*)d_in[3];
    const float* bk = (const float*)d_in[4];
    const float* wv = (const float*)d_in[5];
    const float* bv = (const float*)d_in[6];
    const float* wp = (const float*)d_in[7];
    const float* bp = (const float*)d_in[8];
    float* out = (float*)d_out;

    convert_w<<<64, 256>>>(wq, wk, wv, wp);

    dim3 gemm_grid(PDIM / BN, CDIM / BM, BATCH);     // 500 x 4 x 2
    qkv_gemm<<<gemm_grid, 256>>>(x, bq, bk, bv);

    dim3 attn_grid(SDIM, HD / 2, BATCH * HEADS);     // 40 x 16 x 16
    attn_kernel<<<attn_grid, 256>>>();

    proj_gemm<<<gemm_grid, 256>>>(bp, out);
}

// round 12
// speedup vs baseline: 1.2183x; 1.0244x over previous
#include <cuda_runtime.h>
#include <cstdint>

// Problem constants
#define CDIM   256
#define HEADS  8
#define HD     32
#define SDIM   40          // H == W == D == 40
#define PDIM   64000       // H*W*D
#define BATCH  2

// GEMM tiling (256 threads, 64x128 tile, BK=16)
#define BM 64
#define BN 128
#define BK 16
#define XPAD 8             // X row stride 136; 136 % 32 == 8 -> conflict-free frag gathers
#define KPAD 4             // W row stride 20 floats (80B); ldmatrix rows hit distinct bank quads
#define WS   (BK + KPAD)   // 20

#define WELEMS (CDIM * CDIM)
#define XELEMS (BATCH * CDIM * PDIM)

// Scratch (device globals; no allocation)
__device__ float g_q   [XELEMS];
__device__ float g_k   [XELEMS];
__device__ float g_v   [XELEMS];
__device__ float g_attn[XELEMS];
__device__ float g_wc  [4 * WELEMS];    // wq,wk,wv,wp pre-rounded to tf32

__device__ __forceinline__ uint32_t to_tf32(float x) {
    uint32_t r;
    asm("cvt.rna.tf32.f32 %0, %1;" : "=r"(r) : "f"(x));
    return r;
}
__device__ __forceinline__ float to_tf32f(float x) {
    return __uint_as_float(to_tf32(x));
}

__device__ __forceinline__ void mma_tf32(float* d, const uint32_t* a, const uint32_t* b) {
    asm volatile(
        "mma.sync.aligned.m16n8k8.row.col.f32.tf32.tf32.f32 "
        "{%0,%1,%2,%3}, {%4,%5,%6,%7}, {%8,%9}, {%0,%1,%2,%3};"
        : "+f"(d[0]), "+f"(d[1]), "+f"(d[2]), "+f"(d[3])
        : "r"(a[0]), "r"(a[1]), "r"(a[2]), "r"(a[3]), "r"(b[0]), "r"(b[1]));
}

// ldmatrix x4: loads the full tf32 A-fragment (a0..a3) in one instruction.
// Each 8x8 b16 tile == 8x4 fp32 tile; thread lane gets fp32 (lane>>2, lane&3).
__device__ __forceinline__ void ldsm_x4(uint32_t* r, uint32_t addr) {
    asm volatile("ldmatrix.sync.aligned.m8n8.x4.shared.b16 {%0,%1,%2,%3}, [%4];"
        : "=r"(r[0]), "=r"(r[1]), "=r"(r[2]), "=r"(r[3]) : "r"(addr));
}

__device__ __forceinline__ uint32_t smem_u32(const void* p) {
    return (uint32_t)__cvta_generic_to_shared(p);
}

__device__ __forceinline__ void cp16(void* smem, const void* gmem) {
    asm volatile("cp.async.ca.shared.global [%0], [%1], 16;"
        :: "r"(smem_u32(smem)), "l"(gmem));
}
__device__ __forceinline__ void cp_commit() { asm volatile("cp.async.commit_group;"); }
template <int N>
__device__ __forceinline__ void cp_wait() { asm volatile("cp.async.wait_group %0;" :: "n"(N)); }

// ---------------------------------------------------------------------------
// Kernel 0: one-time TF32 rounding of the four weight matrices.
// ---------------------------------------------------------------------------
__global__ __launch_bounds__(256) void convert_w(
    const float* __restrict__ wq, const float* __restrict__ wk,
    const float* __restrict__ wv, const float* __restrict__ wp)
{
    const int stride = gridDim.x * blockDim.x;
    const int nw4 = WELEMS / 4;
    for (int i = blockIdx.x * blockDim.x + threadIdx.x; i < nw4; i += stride) {
        float4 a = ((const float4*)wq)[i];
        float4 b = ((const float4*)wk)[i];
        float4 c = ((const float4*)wv)[i];
        float4 d = ((const float4*)wp)[i];
        ((float4*)g_wc)[i          ] = {to_tf32f(a.x), to_tf32f(a.y), to_tf32f(a.z), to_tf32f(a.w)};
        ((float4*)g_wc)[i +     nw4] = {to_tf32f(b.x), to_tf32f(b.y), to_tf32f(b.z), to_tf32f(b.w)};
        ((float4*)g_wc)[i + 2 * nw4] = {to_tf32f(c.x), to_tf32f(c.y), to_tf32f(c.z), to_tf32f(c.w)};
        ((float4*)g_wc)[i + 3 * nw4] = {to_tf32f(d.x), to_tf32f(d.y), to_tf32f(d.z), to_tf32f(d.w)};
    }
}

// Per-thread ldmatrix row-address element offset within a W tile.
// tile 0: a0 rows g,   k 0-3 | tile 1: a1 rows g+8, k 0-3
// tile 2: a2 rows g,   k 4-7 | tile 3: a3 rows g+8, k 4-7
__device__ __forceinline__ int ldsm_thread_off(int lane, int wm) {
    int mrow = wm * 32 + (lane & 7) + ((lane >> 3) & 1) * 8;
    int kcol = (lane >> 4) * 4;
    return mrow * WS + kcol;
}

// ---------------------------------------------------------------------------
// Kernel 1: fused QKV 1x1x1 conv, TF32 MMA, cp.async + ldmatrix A-fragments.
// ---------------------------------------------------------------------------
__global__ __launch_bounds__(256, 2) void qkv_gemm(
    const float* __restrict__ x,
    const float* __restrict__ bq, const float* __restrict__ bk,
    const float* __restrict__ bv)
{
    __shared__ __align__(16) float    sX [2][BK][BN + XPAD];   // [k][n]
    __shared__ __align__(16) uint32_t sWq[2][BM][WS];          // [m][k], pre-rounded bits
    __shared__ __align__(16) uint32_t sWk[2][BM][WS];
    __shared__ __align__(16) uint32_t sWv[2][BM][WS];

    const int b    = blockIdx.z;
    const int m0   = blockIdx.y * BM;
    const int n0   = blockIdx.x * BN;
    const int tid  = threadIdx.x;
    const int warp = tid >> 5;
    const int lane = tid & 31;
    const int wm   = warp >> 2;          // 0..1
    const int wn   = warp & 3;           // 0..3
    const int g    = lane >> 2;          // 0..7
    const int t    = lane & 3;           // 0..3

    const float* xb = x + (size_t)b * CDIM * PDIM;
    const float* wq = g_wc;
    const float* wk = g_wc + WELEMS;
    const float* wv = g_wc + 2 * WELEMS;

    // loader indices
    const int xl_kr0 = tid >> 5;
    const int xl_nc  = (tid & 31) * 4;
    const int wl_m   = tid & 63;
    const int wl_k4  = (tid >> 6) << 2;

    // ldmatrix per-thread byte offsets (element offset * 4)
    const int lds_off = ldsm_thread_off(lane, wm) * 4;
    const uint32_t wq_b0 = smem_u32(&sWq[0][0][0]);
    const uint32_t wk_b0 = smem_u32(&sWk[0][0][0]);
    const uint32_t wv_b0 = smem_u32(&sWv[0][0][0]);
    const uint32_t stage_bytes = BM * WS * 4;

    float accq[2][4][4] = {};
    float acck[2][4][4] = {};
    float accv[2][4][4] = {};

    // ---- prologue
    {
        cp16(&sX[0][xl_kr0    ][xl_nc], &xb[(size_t)(xl_kr0    ) * PDIM + n0 + xl_nc]);
        cp16(&sX[0][xl_kr0 + 8][xl_nc], &xb[(size_t)(xl_kr0 + 8) * PDIM + n0 + xl_nc]);
        const size_t widx = (size_t)(m0 + wl_m) * CDIM + wl_k4;
        cp16(&sWq[0][wl_m][wl_k4], &wq[widx]);
        cp16(&sWk[0][wl_m][wl_k4], &wk[widx]);
        cp16(&sWv[0][wl_m][wl_k4], &wv[widx]);
        cp_commit();
    }

    const int NT = CDIM / BK;   // 16
    for (int it = 0; it < NT; it++) {
        const int st = it & 1;
        if (it + 1 < NT) {
            const int ns = st ^ 1;
            const int k0 = (it + 1) * BK;
            cp16(&sX[ns][xl_kr0    ][xl_nc], &xb[(size_t)(k0 + xl_kr0    ) * PDIM + n0 + xl_nc]);
            cp16(&sX[ns][xl_kr0 + 8][xl_nc], &xb[(size_t)(k0 + xl_kr0 + 8) * PDIM + n0 + xl_nc]);
            const size_t widx = (size_t)(m0 + wl_m) * CDIM + k0 + wl_k4;
            cp16(&sWq[ns][wl_m][wl_k4], &wq[widx]);
            cp16(&sWk[ns][wl_m][wl_k4], &wk[widx]);
            cp16(&sWv[ns][wl_m][wl_k4], &wv[widx]);
            cp_commit();
            cp_wait<1>();
        } else {
            cp_wait<0>();
        }
        __syncthreads();

        const float (*X)[BN + XPAD] = sX[st];
        const uint32_t wq_base = wq_b0 + st * stage_bytes + lds_off;
        const uint32_t wk_base = wk_b0 + st * stage_bytes + lds_off;
        const uint32_t wv_base = wv_b0 + st * stage_bytes + lds_off;

        #pragma unroll
        for (int ks = 0; ks < BK; ks += 8) {
            uint32_t bf[4][2];
            #pragma unroll
            for (int ni = 0; ni < 4; ni++) {
                int ncol = wn * 32 + ni * 8 + g;
                bf[ni][0] = to_tf32(X[ks + t    ][ncol]);
                bf[ni][1] = to_tf32(X[ks + t + 4][ncol]);
            }
            #pragma unroll
            for (int mat = 0; mat < 3; mat++) {
                const uint32_t wbase = (mat == 0) ? wq_base : (mat == 1) ? wk_base : wv_base;
                float (*acc)[4][4]   = (mat == 0) ? accq : (mat == 1) ? acck : accv;
                #pragma unroll
                for (int mi = 0; mi < 2; mi++) {
                    uint32_t af[4];
                    ldsm_x4(af, wbase + (mi * 16 * WS + ks) * 4);
                    #pragma unroll
                    for (int ni = 0; ni < 4; ni++)
                        mma_tf32(acc[mi][ni], af, bf[ni]);
                }
            }
        }
        __syncthreads();
    }

    // Epilogue: bias + store
    #pragma unroll
    for (int mi = 0; mi < 2; mi++) {
        #pragma unroll
        for (int rr = 0; rr < 2; rr++) {
            const int m  = m0 + wm * 32 + mi * 16 + g + rr * 8;
            const float biq = bq[m], bik = bk[m], biv = bv[m];
            const size_t rowbase = ((size_t)b * CDIM + m) * PDIM;
            #pragma unroll
            for (int ni = 0; ni < 4; ni++) {
                const size_t o = rowbase + n0 + wn * 32 + ni * 8 + t * 2;
                float2 vq = {accq[mi][ni][rr * 2] + biq, accq[mi][ni][rr * 2 + 1] + biq};
                float2 vk = {acck[mi][ni][rr * 2] + bik, acck[mi][ni][rr * 2 + 1] + bik};
                float2 vv = {accv[mi][ni][rr * 2] + biv, accv[mi][ni][rr * 2 + 1] + biv};
                *(float2*)&g_q[o] = vq;
                *(float2*)&g_k[o] = vk;
                *(float2*)&g_v[o] = vv;
            }
        }
    }
}

// ---------------------------------------------------------------------------
// Kernel 2: attention (three reference branches are bitwise-identical
// reshapes since H==W==D -> compute one, scale by 3).
// 2 channels per block; S overlays dead Q tile; output pre-rounded to tf32.
// ---------------------------------------------------------------------------
__global__ __launch_bounds__(256) void attn_kernel()
{
    __shared__ float sQ[2][40][41];
    __shared__ float sK[2][40][41];
    __shared__ float sV[2][40][41];

    const int s1    = blockIdx.x;
    const int cpair = blockIdx.y;
    const int bh    = blockIdx.z;
    const int tid   = threadIdx.x;
    const int half  = tid >> 7;
    const int t2    = tid & 127;

    const int c = cpair * 2 + half;
    const size_t base = (size_t)(bh * HD + c) * PDIM + s1 * 1600;

    for (int e = t2; e < 1600; e += 128) {
        int r  = e / 40;
        int cc = e - r * 40;
        sQ[half][r][cc] = g_q[base + e];
        sK[half][r][cc] = g_k[base + e];
        sV[half][r][cc] = g_v[base + e];
    }
    __syncthreads();

    const float scale = 0.17677669529663687f;   // 32^-0.5
    const int i0 = (t2 / 10) * 4;
    const int j0 = (t2 % 10) * 4;

    float acc[4][4] = {};
    if (t2 < 100) {
        #pragma unroll 8
        for (int k = 0; k < 40; k++) {
            float qv[4], kv[4];
            #pragma unroll
            for (int a = 0; a < 4; a++) { qv[a] = sQ[half][i0 + a][k]; kv[a] = sK[half][j0 + a][k]; }
            #pragma unroll
            for (int a = 0; a < 4; a++)
                #pragma unroll
                for (int bb = 0; bb < 4; bb++)
                    acc[a][bb] = fmaf(qv[a], kv[bb], acc[a][bb]);
        }
    }
    __syncthreads();
    if (t2 < 100) {
        #pragma unroll
        for (int a = 0; a < 4; a++)
            #pragma unroll
            for (int bb = 0; bb < 4; bb++)
                sQ[half][i0 + a][j0 + bb] = acc[a][bb] * scale;
    }
    __syncthreads();

    if (t2 < 40) {
        float mx = -1e30f;
        #pragma unroll 8
        for (int j = 0; j < 40; j++) mx = fmaxf(mx, sQ[half][t2][j]);
        float sum = 0.0f;
        #pragma unroll 8
        for (int j = 0; j < 40; j++) {
            float ev = __expf(sQ[half][t2][j] - mx);
            sQ[half][t2][j] = ev;
            sum += ev;
        }
        const float inv = 1.0f / sum;
        #pragma unroll 8
        for (int j = 0; j < 40; j++) sQ[half][t2][j] *= inv;
    }
    __syncthreads();

    if (t2 < 100) {
        float acc2[4][4] = {};
        #pragma unroll 8
        for (int k = 0; k < 40; k++) {
            float av[4], vv[4];
            #pragma unroll
            for (int a = 0; a < 4; a++) { av[a] = sQ[half][i0 + a][k]; vv[a] = sV[half][k][j0 + a]; }
            #pragma unroll
            for (int a = 0; a < 4; a++)
                #pragma unroll
                for (int bb = 0; bb < 4; bb++)
                    acc2[a][bb] = fmaf(av[a], vv[bb], acc2[a][bb]);
        }
        #pragma unroll
        for (int a = 0; a < 4; a++) {
            float4 o = {to_tf32f(3.0f * acc2[a][0]), to_tf32f(3.0f * acc2[a][1]),
                        to_tf32f(3.0f * acc2[a][2]), to_tf32f(3.0f * acc2[a][3])};
            *(float4*)&g_attn[base + (size_t)(i0 + a) * 40 + j0] = o;
        }
    }
}

// ---------------------------------------------------------------------------
// Kernel 3: output projection, TF32 MMA + cp.async + ldmatrix, zero CVTs.
// ---------------------------------------------------------------------------
__global__ __launch_bounds__(256, 2) void proj_gemm(
    const float* __restrict__ bp, float* __restrict__ out)
{
    __shared__ __align__(16) uint32_t sX[2][BK][BN + XPAD];
    __shared__ __align__(16) uint32_t sW[2][BM][WS];

    const int b    = blockIdx.z;
    const int m0   = blockIdx.y * BM;
    const int n0   = blockIdx.x * BN;
    const int tid  = threadIdx.x;
    const int warp = tid >> 5;
    const int lane = tid & 31;
    const int wm   = warp >> 2;
    const int wn   = warp & 3;
    const int g    = lane >> 2;
    const int t    = lane & 3;

    const float* xb = g_attn + (size_t)b * CDIM * PDIM;
    const float* wp = g_wc + 3 * WELEMS;

    const int xl_kr0 = tid >> 5;
    const int xl_nc  = (tid & 31) * 4;
    const int wl_m   = tid & 63;
    const int wl_k4  = (tid >> 6) << 2;

    const int lds_off = ldsm_thread_off(lane, wm) * 4;
    const uint32_t w_b0 = smem_u32(&sW[0][0][0]);
    const uint32_t stage_bytes = BM * WS * 4;

    float acc[2][4][4] = {};

    {
        cp16(&sX[0][xl_kr0    ][xl_nc], &xb[(size_t)(xl_kr0    ) * PDIM + n0 + xl_nc]);
        cp16(&sX[0][xl_kr0 + 8][xl_nc], &xb[(size_t)(xl_kr0 + 8) * PDIM + n0 + xl_nc]);
        cp16(&sW[0][wl_m][wl_k4], &wp[(size_t)(m0 + wl_m) * CDIM + wl_k4]);
        cp_commit();
    }

    const int NT = CDIM / BK;
    for (int it = 0; it < NT; it++) {
        const int st = it & 1;
        if (it + 1 < NT) {
            const int ns = st ^ 1;
            const int k0 = (it + 1) * BK;
            cp16(&sX[ns][xl_kr0    ][xl_nc], &xb[(size_t)(k0 + xl_kr0    ) * PDIM + n0 + xl_nc]);
            cp16(&sX[ns][xl_kr0 + 8][xl_nc], &xb[(size_t)(k0 + xl_kr0 + 8) * PDIM + n0 + xl_nc]);
            cp16(&sW[ns][wl_m][wl_k4], &wp[(size_t)(m0 + wl_m) * CDIM + k0 + wl_k4]);
            cp_commit();
            cp_wait<1>();
        } else {
            cp_wait<0>();
        }
        __syncthreads();

        const uint32_t (*X)[BN + XPAD] = sX[st];
        const uint32_t w_base = w_b0 + st * stage_bytes + lds_off;

        #pragma unroll
        for (int ks = 0; ks < BK; ks += 8) {
            uint32_t bf[4][2];
            #pragma unroll
            for (int ni = 0; ni < 4; ni++) {
                int ncol = wn * 32 + ni * 8 + g;
                bf[ni][0] = X[ks + t    ][ncol];
                bf[ni][1] = X[ks + t + 4][ncol];
            }
            #pragma unroll
            for (int mi = 0; mi < 2; mi++) {
                uint32_t af[4];
                ldsm_x4(af, w_base + (mi * 16 * WS + ks) * 4);
                #pragma unroll
                for (int ni = 0; ni < 4; ni++)
                    mma_tf32(acc[mi][ni], af, bf[ni]);
            }
        }
        __syncthreads();
    }

    #pragma unroll
    for (int mi = 0; mi < 2; mi++) {
        #pragma unroll
        for (int rr = 0; rr < 2; rr++) {
            const int m  = m0 + wm * 32 + mi * 16 + g + rr * 8;
            const float bi = bp[m];
            const size_t rowbase = ((size_t)b * CDIM + m) * PDIM;
            #pragma unroll
            for (int ni = 0; ni < 4; ni++) {
                const size_t o = rowbase + n0 + wn * 32 + ni * 8 + t * 2;
                float2 v = {acc[mi][ni][rr * 2] + bi, acc[mi][ni][rr * 2 + 1] + bi};
                *(float2*)&out[o] = v;
            }
        }
    }
}

// ---------------------------------------------------------------------------
extern "C" void kernel_launch(void* const* d_in, const int* in_sizes, int n_in,
                              void* d_out, int out_size)
{
    const float* x  = (const float*)d_in[0];
    const float* wq = (const float*)d_in[1];
    const float* bq = (const float*)d_in[2];
    const float* wk = (const float*)d_in[3];
    const float* bk = (const float*)d_in[4];
    const float* wv = (const float*)d_in[5];
    const float* bv = (const float*)d_in[6];
    const float* wp = (const float*)d_in[7];
    const float* bp = (const float*)d_in[8];
    float* out = (float*)d_out;

    convert_w<<<64, 256>>>(wq, wk, wv, wp);

    dim3 gemm_grid(PDIM / BN, CDIM / BM, BATCH);     // 500 x 4 x 2
    qkv_gemm<<<gemm_grid, 256>>>(x, bq, bk, bv);

    dim3 attn_grid(SDIM, HD / 2, BATCH * HEADS);     // 40 x 16 x 16
    attn_kernel<<<attn_grid, 256>>>();

    proj_gemm<<<gemm_grid, 256>>>(bp, out);
}

// round 13
// speedup vs baseline: 1.4002x; 1.1493x over previous
#include <cuda_runtime.h>
#include <cstdint>

// Problem constants
#define CDIM   256
#define HEADS  8
#define HD     32
#define SDIM   40          // H == W == D == 40
#define PDIM   64000       // H*W*D
#define BATCH  2

// GEMM tiling: 128 threads, 2x2 warps of 64x64, BM=BN=128, BK=16
#define BM 128
#define BN 128
#define BK 16
#define XPAD 8             // X row stride 136; (8t+g+8ni) mod 32 distinct -> conflict-free
#define KPAD 4             // W row stride 20; ldmatrix rows cover all bank quads
#define WS   (BK + KPAD)   // 20
#define MI   4             // m16 tiles per warp
#define NI   8             // n8 tiles per warp

#define WELEMS (CDIM * CDIM)
#define XELEMS (BATCH * CDIM * PDIM)

// Scratch (device globals; no allocation)
__device__ float g_q   [XELEMS];
__device__ float g_k   [XELEMS];
__device__ float g_v   [XELEMS];
__device__ float g_attn[XELEMS];
__device__ float g_wc  [4 * WELEMS];    // [wq;wk;wv;wp] pre-rounded to tf32, row-contiguous

__device__ __forceinline__ uint32_t to_tf32(float x) {
    uint32_t r;
    asm("cvt.rna.tf32.f32 %0, %1;" : "=r"(r) : "f"(x));
    return r;
}
__device__ __forceinline__ float to_tf32f(float x) {
    return __uint_as_float(to_tf32(x));
}

__device__ __forceinline__ void mma_tf32(float* d, const uint32_t* a, const uint32_t* b) {
    asm volatile(
        "mma.sync.aligned.m16n8k8.row.col.f32.tf32.tf32.f32 "
        "{%0,%1,%2,%3}, {%4,%5,%6,%7}, {%8,%9}, {%0,%1,%2,%3};"
        : "+f"(d[0]), "+f"(d[1]), "+f"(d[2]), "+f"(d[3])
        : "r"(a[0]), "r"(a[1]), "r"(a[2]), "r"(a[3]), "r"(b[0]), "r"(b[1]));
}

// ldmatrix x4: one full tf32 m16k8 A-fragment per instruction.
__device__ __forceinline__ void ldsm_x4(uint32_t* r, uint32_t addr) {
    asm volatile("ldmatrix.sync.aligned.m8n8.x4.shared.b16 {%0,%1,%2,%3}, [%4];"
        : "=r"(r[0]), "=r"(r[1]), "=r"(r[2]), "=r"(r[3]) : "r"(addr));
}

__device__ __forceinline__ uint32_t smem_u32(const void* p) {
    return (uint32_t)__cvta_generic_to_shared(p);
}
__device__ __forceinline__ void cp16(void* smem, const void* gmem) {
    asm volatile("cp.async.ca.shared.global [%0], [%1], 16;"
        :: "r"(smem_u32(smem)), "l"(gmem));
}
__device__ __forceinline__ void cp_commit() { asm volatile("cp.async.commit_group;"); }
template <int N>
__device__ __forceinline__ void cp_wait() { asm volatile("cp.async.wait_group %0;" :: "n"(N)); }

// ---------------------------------------------------------------------------
// Kernel 0: one-time TF32 rounding of the four weight matrices.
// ---------------------------------------------------------------------------
__global__ __launch_bounds__(256) void convert_w(
    const float* __restrict__ wq, const float* __restrict__ wk,
    const float* __restrict__ wv, const float* __restrict__ wp)
{
    const int stride = gridDim.x * blockDim.x;
    const int nw4 = WELEMS / 4;
    for (int i = blockIdx.x * blockDim.x + threadIdx.x; i < nw4; i += stride) {
        float4 a = ((const float4*)wq)[i];
        float4 b = ((const float4*)wk)[i];
        float4 c = ((const float4*)wv)[i];
        float4 d = ((const float4*)wp)[i];
        ((float4*)g_wc)[i          ] = {to_tf32f(a.x), to_tf32f(a.y), to_tf32f(a.z), to_tf32f(a.w)};
        ((float4*)g_wc)[i +     nw4] = {to_tf32f(b.x), to_tf32f(b.y), to_tf32f(b.z), to_tf32f(b.w)};
        ((float4*)g_wc)[i + 2 * nw4] = {to_tf32f(c.x), to_tf32f(c.y), to_tf32f(c.z), to_tf32f(c.w)};
        ((float4*)g_wc)[i + 3 * nw4] = {to_tf32f(d.x), to_tf32f(d.y), to_tf32f(d.z), to_tf32f(d.w)};
    }
}

// Per-thread ldmatrix element offset within a W stage (rows mrow, k chunk).
__device__ __forceinline__ int ldsm_thread_off(int lane, int wm) {
    int mrow = wm * 64 + (lane & 7) + ((lane >> 3) & 1) * 8;
    int kcol = (lane >> 4) * 4;
    return mrow * WS + kcol;
}

// ---------------------------------------------------------------------------
// Kernel 1: stacked QKV GEMM: M=768 ([wq;wk;wv] rows), N=64000, K=256.
// 128 threads, warp tile 64x64, TF32 MMA + cp.async + ldmatrix.
// Each CTA's 128 m-rows lie inside one matrix (256 = 2*128).
// ---------------------------------------------------------------------------
__global__ __launch_bounds__(128) void qkv_gemm(
    const float* __restrict__ x,
    const float* __restrict__ bq, const float* __restrict__ bk,
    const float* __restrict__ bv)
{
    __shared__ __align__(16) float    sX[2][BK][BN + XPAD];   // [k][n]
    __shared__ __align__(16) uint32_t sW[2][BM][WS];          // [m][k] pre-rounded bits

    const int b    = blockIdx.z;
    const int m0   = blockIdx.y * BM;          // 0..640, within stacked 768
    const int n0   = blockIdx.x * BN;
    const int mat  = blockIdx.y >> 1;          // 0=q, 1=k, 2=v
    const int tid  = threadIdx.x;
    const int warp = tid >> 5;
    const int lane = tid & 31;
    const int wm   = warp >> 1;                // 0..1
    const int wn   = warp & 1;                 // 0..1
    const int g    = lane >> 2;                // 0..7
    const int t    = lane & 3;                 // 0..3

    const float* xb = x + (size_t)b * CDIM * PDIM;
    const float* bias = (mat == 0) ? bq : (mat == 1) ? bk : bv;
    float* outp = (mat == 0) ? g_q : (mat == 1) ? g_k : g_v;

    // loaders: X tile 16x128 = 512 float4 -> 4 per thread; W 128x16 = 512 f4 -> 4
    const int lds_off = ldsm_thread_off(lane, wm) * 4;
    const uint32_t w_b0 = smem_u32(&sW[0][0][0]);
    const uint32_t stage_bytes = BM * WS * 4;

    float acc[MI][NI][4] = {};

    // ---- prologue: stage 0
    {
        #pragma unroll
        for (int i = 0; i < 4; i++) {
            int idx = tid + i * 128;
            int kr  = idx >> 5;
            int nc  = (idx & 31) * 4;
            cp16(&sX[0][kr][nc], &xb[(size_t)kr * PDIM + n0 + nc]);
        }
        #pragma unroll
        for (int kk = 0; kk < 16; kk += 4)
            cp16(&sW[0][tid][kk], &g_wc[(size_t)(m0 + tid) * CDIM + kk]);
        cp_commit();
    }

    const int NT = CDIM / BK;   // 16
    for (int it = 0; it < NT; it++) {
        const int st = it & 1;
        if (it + 1 < NT) {
            const int ns = st ^ 1;
            const int k0 = (it + 1) * BK;
            #pragma unroll
            for (int i = 0; i < 4; i++) {
                int idx = tid + i * 128;
                int kr  = idx >> 5;
                int nc  = (idx & 31) * 4;
                cp16(&sX[ns][kr][nc], &xb[(size_t)(k0 + kr) * PDIM + n0 + nc]);
            }
            #pragma unroll
            for (int kk = 0; kk < 16; kk += 4)
                cp16(&sW[ns][tid][kk], &g_wc[(size_t)(m0 + tid) * CDIM + k0 + kk]);
            cp_commit();
            cp_wait<1>();
        } else {
            cp_wait<0>();
        }
        __syncthreads();

        const float (*X)[BN + XPAD] = sX[st];
        const uint32_t w_base = w_b0 + st * stage_bytes + lds_off;

        #pragma unroll
        for (int ks = 0; ks < BK; ks += 8) {
            uint32_t bf[NI][2];
            #pragma unroll
            for (int ni = 0; ni < NI; ni++) {
                int ncol = wn * 64 + ni * 8 + g;
                bf[ni][0] = to_tf32(X[ks + t    ][ncol]);
                bf[ni][1] = to_tf32(X[ks + t + 4][ncol]);
            }
            #pragma unroll
            for (int mi = 0; mi < MI; mi++) {
                uint32_t af[4];
                ldsm_x4(af, w_base + (mi * 16 * WS + ks) * 4);
                #pragma unroll
                for (int ni = 0; ni < NI; ni++)
                    mma_tf32(acc[mi][ni], af, bf[ni]);
            }
        }
        __syncthreads();
    }

    // Epilogue: bias + store (row within matrix = m & 255)
    #pragma unroll
    for (int mi = 0; mi < MI; mi++) {
        #pragma unroll
        for (int rr = 0; rr < 2; rr++) {
            const int m  = m0 + wm * 64 + mi * 16 + g + rr * 8;
            const int c  = m & 255;
            const float bi = bias[c];
            const size_t rowbase = ((size_t)b * CDIM + c) * PDIM;
            #pragma unroll
            for (int ni = 0; ni < NI; ni++) {
                const size_t o = rowbase + n0 + wn * 64 + ni * 8 + t * 2;
                float2 v = {acc[mi][ni][rr * 2] + bi, acc[mi][ni][rr * 2 + 1] + bi};
                *(float2*)&outp[o] = v;
            }
        }
    }
}

// ---------------------------------------------------------------------------
// Kernel 2: attention (three reference branches are bitwise-identical
// reshapes since H==W==D -> compute one, scale by 3).
// 2 channels per block; S overlays dead Q tile; output pre-rounded to tf32.
// ---------------------------------------------------------------------------
__global__ __launch_bounds__(256) void attn_kernel()
{
    __shared__ float sQ[2][40][41];
    __shared__ float sK[2][40][41];
    __shared__ float sV[2][40][41];

    const int s1    = blockIdx.x;
    const int cpair = blockIdx.y;
    const int bh    = blockIdx.z;
    const int tid   = threadIdx.x;
    const int half  = tid >> 7;
    const int t2    = tid & 127;

    const int c = cpair * 2 + half;
    const size_t base = (size_t)(bh * HD + c) * PDIM + s1 * 1600;

    for (int e = t2; e < 1600; e += 128) {
        int r  = e / 40;
        int cc = e - r * 40;
        sQ[half][r][cc] = g_q[base + e];
        sK[half][r][cc] = g_k[base + e];
        sV[half][r][cc] = g_v[base + e];
    }
    __syncthreads();

    const float scale = 0.17677669529663687f;   // 32^-0.5
    const int i0 = (t2 / 10) * 4;
    const int j0 = (t2 % 10) * 4;

    float acc[4][4] = {};
    if (t2 < 100) {
        #pragma unroll 8
        for (int k = 0; k < 40; k++) {
            float qv[4], kv[4];
            #pragma unroll
            for (int a = 0; a < 4; a++) { qv[a] = sQ[half][i0 + a][k]; kv[a] = sK[half][j0 + a][k]; }
            #pragma unroll
            for (int a = 0; a < 4; a++)
                #pragma unroll
                for (int bb = 0; bb < 4; bb++)
                    acc[a][bb] = fmaf(qv[a], kv[bb], acc[a][bb]);
        }
    }
    __syncthreads();
    if (t2 < 100) {
        #pragma unroll
        for (int a = 0; a < 4; a++)
            #pragma unroll
            for (int bb = 0; bb < 4; bb++)
                sQ[half][i0 + a][j0 + bb] = acc[a][bb] * scale;
    }
    __syncthreads();

    if (t2 < 40) {
        float mx = -1e30f;
        #pragma unroll 8
        for (int j = 0; j < 40; j++) mx = fmaxf(mx, sQ[half][t2][j]);
        float sum = 0.0f;
        #pragma unroll 8
        for (int j = 0; j < 40; j++) {
            float ev = __expf(sQ[half][t2][j] - mx);
            sQ[half][t2][j] = ev;
            sum += ev;
        }
        const float inv = 1.0f / sum;
        #pragma unroll 8
        for (int j = 0; j < 40; j++) sQ[half][t2][j] *= inv;
    }
    __syncthreads();

    if (t2 < 100) {
        float acc2[4][4] = {};
        #pragma unroll 8
        for (int k = 0; k < 40; k++) {
            float av[4], vv[4];
            #pragma unroll
            for (int a = 0; a < 4; a++) { av[a] = sQ[half][i0 + a][k]; vv[a] = sV[half][k][j0 + a]; }
            #pragma unroll
            for (int a = 0; a < 4; a++)
                #pragma unroll
                for (int bb = 0; bb < 4; bb++)
                    acc2[a][bb] = fmaf(av[a], vv[bb], acc2[a][bb]);
        }
        #pragma unroll
        for (int a = 0; a < 4; a++) {
            float4 o = {to_tf32f(3.0f * acc2[a][0]), to_tf32f(3.0f * acc2[a][1]),
                        to_tf32f(3.0f * acc2[a][2]), to_tf32f(3.0f * acc2[a][3])};
            *(float4*)&g_attn[base + (size_t)(i0 + a) * 40 + j0] = o;
        }
    }
}

// ---------------------------------------------------------------------------
// Kernel 3: output projection (M=256), same 64x64-warp shape, zero CVTs
// (g_attn pre-rounded; wp pre-rounded at g_wc rows 768..1023).
// ---------------------------------------------------------------------------
__global__ __launch_bounds__(128) void proj_gemm(
    const float* __restrict__ bp, float* __restrict__ out)
{
    __shared__ __align__(16) uint32_t sX[2][BK][BN + XPAD];
    __shared__ __align__(16) uint32_t sW[2][BM][WS];

    const int b    = blockIdx.z;
    const int m0   = blockIdx.y * BM;          // 0 or 128
    const int n0   = blockIdx.x * BN;
    const int tid  = threadIdx.x;
    const int warp = tid >> 5;
    const int lane = tid & 31;
    const int wm   = warp >> 1;
    const int wn   = warp & 1;
    const int g    = lane >> 2;
    const int t    = lane & 3;

    const float* xb = g_attn + (size_t)b * CDIM * PDIM;
    const int wrow0 = 3 * CDIM + m0;           // wp rows within g_wc

    const int lds_off = ldsm_thread_off(lane, wm) * 4;
    const uint32_t w_b0 = smem_u32(&sW[0][0][0]);
    const uint32_t stage_bytes = BM * WS * 4;

    float acc[MI][NI][4] = {};

    {
        #pragma unroll
        for (int i = 0; i < 4; i++) {
            int idx = tid + i * 128;
            int kr  = idx >> 5;
            int nc  = (idx & 31) * 4;
            cp16(&sX[0][kr][nc], &xb[(size_t)kr * PDIM + n0 + nc]);
        }
        #pragma unroll
        for (int kk = 0; kk < 16; kk += 4)
            cp16(&sW[0][tid][kk], &g_wc[(size_t)(wrow0 + tid) * CDIM + kk]);
        cp_commit();
    }

    const int NT = CDIM / BK;
    for (int it = 0; it < NT; it++) {
        const int st = it & 1;
        if (it + 1 < NT) {
            const int ns = st ^ 1;
            const int k0 = (it + 1) * BK;
            #pragma unroll
            for (int i = 0; i < 4; i++) {
                int idx = tid + i * 128;
                int kr  = idx >> 5;
                int nc  = (idx & 31) * 4;
                cp16(&sX[ns][kr][nc], &xb[(size_t)(k0 + kr) * PDIM + n0 + nc]);
            }
            #pragma unroll
            for (int kk = 0; kk < 16; kk += 4)
                cp16(&sW[ns][tid][kk], &g_wc[(size_t)(wrow0 + tid) * CDIM + k0 + kk]);
            cp_commit();
            cp_wait<1>();
        } else {
            cp_wait<0>();
        }
        __syncthreads();

        const uint32_t (*X)[BN + XPAD] = sX[st];
        const uint32_t w_base = w_b0 + st * stage_bytes + lds_off;

        #pragma unroll
        for (int ks = 0; ks < BK; ks += 8) {
            uint32_t bf[NI][2];
            #pragma unroll
            for (int ni = 0; ni < NI; ni++) {
                int ncol = wn * 64 + ni * 8 + g;
                bf[ni][0] = X[ks + t    ][ncol];
                bf[ni][1] = X[ks + t + 4][ncol];
            }
            #pragma unroll
            for (int mi = 0; mi < MI; mi++) {
                uint32_t af[4];
                ldsm_x4(af, w_base + (mi * 16 * WS + ks) * 4);
                #pragma unroll
                for (int ni = 0; ni < NI; ni++)
                    mma_tf32(acc[mi][ni], af, bf[ni]);
            }
        }
        __syncthreads();
    }

    #pragma unroll
    for (int mi = 0; mi < MI; mi++) {
        #pragma unroll
        for (int rr = 0; rr < 2; rr++) {
            const int m  = m0 + wm * 64 + mi * 16 + g + rr * 8;
            const float bi = bp[m];
            const size_t rowbase = ((size_t)b * CDIM + m) * PDIM;
            #pragma unroll
            for (int ni = 0; ni < NI; ni++) {
                const size_t o = rowbase + n0 + wn * 64 + ni * 8 + t * 2;
                float2 v = {acc[mi][ni][rr * 2] + bi, acc[mi][ni][rr * 2 + 1] + bi};
                *(float2*)&out[o] = v;
            }
        }
    }
}

// ---------------------------------------------------------------------------
extern "C" void kernel_launch(void* const* d_in, const int* in_sizes, int n_in,
                              void* d_out, int out_size)
{
    const float* x  = (const float*)d_in[0];
    const float* wq = (const float*)d_in[1];
    const float* bq = (const float*)d_in[2];
    const float* wk = (const float*)d_in[3];
    const float* bk = (const float*)d_in[4];
    const float* wv = (const float*)d_in[5];
    const float* bv = (const float*)d_in[6];
    const float* wp = (const float*)d_in[7];
    const float* bp = (const float*)d_in[8];
    float* out = (float*)d_out;

    convert_w<<<64, 256>>>(wq, wk, wv, wp);

    dim3 qkv_grid(PDIM / BN, 3 * CDIM / BM, BATCH);   // 500 x 6 x 2
    qkv_gemm<<<qkv_grid, 128>>>(x, bq, bk, bv);

    dim3 attn_grid(SDIM, HD / 2, BATCH * HEADS);      // 40 x 16 x 16
    attn_kernel<<<attn_grid, 256>>>();

    dim3 proj_grid(PDIM / BN, CDIM / BM, BATCH);      // 500 x 2 x 2
    proj_gemm<<<proj_grid, 128>>>(bp, out);
}

// round 16
// speedup vs baseline: 1.6263x; 1.1615x over previous
#include <cuda_runtime.h>
#include <cuda_fp16.h>
#include <cstdint>

// Problem constants
#define CDIM   256
#define HEADS  8
#define HD     32
#define SDIM   40          // H == W == D == 40
#define PDIM   64000       // H*W*D
#define BATCH  2

// GEMM tiling: 128 threads, 2x2 warps of 64x64, CTA 128m x 128n, BK=32 (fp16)
#define BM 128
#define BN 128
#define BKT 32
#define NTK (CDIM / BKT)   // 8
#define ROWH 40            // halves per smem row (64B data + 16B pad = 80B)
#define MI  4              // m16 tiles per warp
#define NI  8              // n8 tiles per warp

#define WELEMS (CDIM * CDIM)
#define XELEMS (BATCH * CDIM * PDIM)

// Scratch (device globals; no allocation)
__device__ float  g_q   [XELEMS];
__device__ float  g_k   [XELEMS];
__device__ float  g_v   [XELEMS];
__device__ float  g_attn[XELEMS];
__device__ __half g_wc  [4 * WELEMS];   // [wq;wk;wv;wp] pre-converted to fp16

__device__ __forceinline__ void mma_f16(float* d, const uint32_t* a, const uint32_t* b) {
    asm volatile(
        "mma.sync.aligned.m16n8k16.row.col.f32.f16.f16.f32 "
        "{%0,%1,%2,%3}, {%4,%5,%6,%7}, {%8,%9}, {%0,%1,%2,%3};"
        : "+f"(d[0]), "+f"(d[1]), "+f"(d[2]), "+f"(d[3])
        : "r"(a[0]), "r"(a[1]), "r"(a[2]), "r"(a[3]), "r"(b[0]), "r"(b[1]));
}

__device__ __forceinline__ void ldsm_x4(uint32_t* r, uint32_t addr) {
    asm volatile("ldmatrix.sync.aligned.m8n8.x4.shared.b16 {%0,%1,%2,%3}, [%4];"
        : "=r"(r[0]), "=r"(r[1]), "=r"(r[2]), "=r"(r[3]) : "r"(addr));
}

__device__ __forceinline__ uint32_t smem_u32(const void* p) {
    return (uint32_t)__cvta_generic_to_shared(p);
}
__device__ __forceinline__ void cp16(void* smem, const void* gmem) {
    asm volatile("cp.async.ca.shared.global [%0], [%1], 16;"
        :: "r"(smem_u32(smem)), "l"(gmem));
}
__device__ __forceinline__ void cp_commit() { asm volatile("cp.async.commit_group;"); }
template <int N>
__device__ __forceinline__ void cp_wait() { asm volatile("cp.async.wait_group %0;" :: "n"(N)); }

// ---------------------------------------------------------------------------
// Kernel 0: one-time fp16 conversion of the four weight matrices.
// ---------------------------------------------------------------------------
__global__ __launch_bounds__(256) void convert_w(
    const float* __restrict__ wq, const float* __restrict__ wk,
    const float* __restrict__ wv, const float* __restrict__ wp)
{
    const int stride = gridDim.x * blockDim.x;
    const int nw4 = WELEMS / 4;
    __half2* dst = (__half2*)g_wc;
    for (int i = blockIdx.x * blockDim.x + threadIdx.x; i < nw4; i += stride) {
        float4 a = ((const float4*)wq)[i];
        float4 b = ((const float4*)wk)[i];
        float4 c = ((const float4*)wv)[i];
        float4 d = ((const float4*)wp)[i];
        dst[                 i * 2    ] = __floats2half2_rn(a.x, a.y);
        dst[                 i * 2 + 1] = __floats2half2_rn(a.z, a.w);
        dst[WELEMS / 2     + i * 2    ] = __floats2half2_rn(b.x, b.y);
        dst[WELEMS / 2     + i * 2 + 1] = __floats2half2_rn(b.z, b.w);
        dst[WELEMS         + i * 2    ] = __floats2half2_rn(c.x, c.y);
        dst[WELEMS         + i * 2 + 1] = __floats2half2_rn(c.z, c.w);
        dst[3 * WELEMS / 2 + i * 2    ] = __floats2half2_rn(d.x, d.y);
        dst[3 * WELEMS / 2 + i * 2 + 1] = __floats2half2_rn(d.z, d.w);
    }
}

// ---------------------------------------------------------------------------
// fp16 GEMM body: out[c][n] = sum_k W[wrow0+c][k] * X[k][n] + bias[c]
// A = W [m][k] fp16 (cp.async), B = X^T [n][k] fp16 (LDG transpose + cvt).
// 80B rows -> conflict-free ldmatrix + STS.128. Double-buffered.
// ---------------------------------------------------------------------------
__device__ __forceinline__ void hgemm_body(
    const float* __restrict__ xsrc, const __half* __restrict__ wsrc_base,
    const float* __restrict__ bias, int bias_mask,
    float* __restrict__ outp)
{
    __shared__ __align__(16) __half sX[2][BN][ROWH];
    __shared__ __align__(16) __half sW[2][BM][ROWH];

    const int n0   = blockIdx.x * BN;
    const int tid  = threadIdx.x;
    const int warp = tid >> 5;
    const int lane = tid & 31;
    const int wm   = warp >> 1;
    const int wn   = warp & 1;
    const int g    = lane >> 2;
    const int t    = lane & 3;

    // ldmatrix per-thread byte offsets (row*80 + 16B chunk)
    const int a_off = (wm * 64 + (lane & 7) + ((lane >> 3) & 1) * 8) * 80 + (lane >> 4) * 16;
    const int b_off = (wn * 64 + ((lane >> 4) & 1) * 8 + (lane & 7)) * 80 + ((lane >> 3) & 1) * 16;
    const uint32_t sW0 = smem_u32(&sW[0][0][0]);
    const uint32_t sX0 = smem_u32(&sX[0][0][0]);
    const uint32_t stage_b = BM * ROWH * 2;   // 10240 bytes

    float acc[MI][NI][4] = {};

    // ---- X transpose fill: thread = n row; 32 strided LDGs -> fp16 -> 4 STS.128
    #define FILL_X(J, S) do { \
        const float* xp = xsrc + (size_t)((J) * BKT) * PDIM + n0 + tid; \
        _Pragma("unroll") \
        for (int q = 0; q < 4; q++) { \
            float v0 = xp[(size_t)(q * 8 + 0) * PDIM]; \
            float v1 = xp[(size_t)(q * 8 + 1) * PDIM]; \
            float v2 = xp[(size_t)(q * 8 + 2) * PDIM]; \
            float v3 = xp[(size_t)(q * 8 + 3) * PDIM]; \
            float v4 = xp[(size_t)(q * 8 + 4) * PDIM]; \
            float v5 = xp[(size_t)(q * 8 + 5) * PDIM]; \
            float v6 = xp[(size_t)(q * 8 + 6) * PDIM]; \
            float v7 = xp[(size_t)(q * 8 + 7) * PDIM]; \
            __half2 h[4]; \
            h[0] = __floats2half2_rn(v0, v1); \
            h[1] = __floats2half2_rn(v2, v3); \
            h[2] = __floats2half2_rn(v4, v5); \
            h[3] = __floats2half2_rn(v6, v7); \
            *(uint4*)((char*)&sX[S][tid][0] + q * 16) = *(uint4*)h; \
        } \
    } while (0)

    // ---- W fill: thread = m row; 4 cp16 covering 32 k halves
    #define FILL_W(J, S) do { \
        const __half* wsrc = wsrc_base + (size_t)tid * CDIM + (J) * BKT; \
        _Pragma("unroll") \
        for (int c = 0; c < 4; c++) \
            cp16((char*)&sW[S][tid][0] + c * 16, wsrc + c * 8); \
        cp_commit(); \
    } while (0)

    FILL_X(0, 0);
    FILL_W(0, 0);

    #pragma unroll 1
    for (int j = 0; j < NTK; j++) {
        const int st = j & 1;
        if (j + 1 < NTK) { FILL_W(j + 1, st ^ 1); cp_wait<1>(); }
        else             { cp_wait<0>(); }
        __syncthreads();
        if (j + 1 < NTK) FILL_X(j + 1, st ^ 1);

        const uint32_t wb = sW0 + st * stage_b + a_off;
        const uint32_t xb = sX0 + st * stage_b + b_off;

        #pragma unroll
        for (int ks = 0; ks < 2; ks++) {          // 2 x k16 per BK32 tile
            uint32_t bf[NI][2];
            #pragma unroll
            for (int p = 0; p < 4; p++) {         // ni pairs
                uint32_t r[4];
                ldsm_x4(r, xb + p * 16 * 80 + ks * 32);
                bf[2 * p    ][0] = r[0]; bf[2 * p    ][1] = r[1];
                bf[2 * p + 1][0] = r[2]; bf[2 * p + 1][1] = r[3];
            }
            #pragma unroll
            for (int mi = 0; mi < MI; mi++) {
                uint32_t af[4];
                ldsm_x4(af, wb + mi * 16 * 80 + ks * 32);
                #pragma unroll
                for (int ni = 0; ni < NI; ni++)
                    mma_f16(acc[mi][ni], af, bf[ni]);
            }
        }
        __syncthreads();
    }

    // Epilogue: bias + coalesced float2 stores
    #pragma unroll
    for (int mi = 0; mi < MI; mi++) {
        #pragma unroll
        for (int rr = 0; rr < 2; rr++) {
            const int m = wm * 64 + mi * 16 + g + rr * 8;
            const int c = m & bias_mask;
            const float bi = bias[c];
            const size_t rowbase = (size_t)c * PDIM;
            #pragma unroll
            for (int ni = 0; ni < NI; ni++) {
                const size_t o = rowbase + n0 + wn * 64 + ni * 8 + t * 2;
                float2 v = {acc[mi][ni][rr * 2] + bi, acc[mi][ni][rr * 2 + 1] + bi};
                *(float2*)&outp[o] = v;
            }
        }
    }
    #undef FILL_X
    #undef FILL_W
}

// Stacked QKV: grid.y = 6 (768 stacked W rows / 128); mat = by>>1.
__global__ __launch_bounds__(128) void qkv_gemm(
    const float* __restrict__ x,
    const float* __restrict__ bq, const float* __restrict__ bk,
    const float* __restrict__ bv)
{
    const int b   = blockIdx.z;
    const int m0  = blockIdx.y * BM;          // within stacked 768
    const int mat = blockIdx.y >> 1;
    const float* bias = (mat == 0) ? bq : (mat == 1) ? bk : bv;
    float* outp = (mat == 0) ? g_q : (mat == 1) ? g_k : g_v;
    const int half128 = blockIdx.y & 1;       // 0 or 1 -> rows 0-127 / 128-255
    hgemm_body(x + (size_t)b * CDIM * PDIM,
               g_wc + (size_t)m0 * CDIM,
               bias + half128 * 128, 127,
               outp + (size_t)b * CDIM * PDIM + (size_t)half128 * 128 * PDIM);
}

__global__ __launch_bounds__(128) void proj_gemm(
    const float* __restrict__ bp, float* __restrict__ out)
{
    const int b = blockIdx.z;
    const int half128 = blockIdx.y;           // 0 or 1
    hgemm_body(g_attn + (size_t)b * CDIM * PDIM,
               g_wc + (size_t)(3 * CDIM + half128 * 128) * CDIM,
               bp + half128 * 128, 127,
               out + (size_t)b * CDIM * PDIM + (size_t)half128 * 128 * PDIM);
}

// ---------------------------------------------------------------------------
// Kernel 2: attention (three reference branches are bitwise-identical
// reshapes since H==W==D -> compute one, scale by 3).
// 2 channels per block; S overlays dead Q tile. Plain fp32 output
// (proj loader does the fp16 rounding).
// ---------------------------------------------------------------------------
__global__ __launch_bounds__(256) void attn_kernel()
{
    __shared__ float sQ[2][40][41];
    __shared__ float sK[2][40][41];
    __shared__ float sV[2][40][41];

    const int s1    = blockIdx.x;
    const int cpair = blockIdx.y;
    const int bh    = blockIdx.z;
    const int tid   = threadIdx.x;
    const int half  = tid >> 7;
    const int t2    = tid & 127;

    const int c = cpair * 2 + half;
    const size_t base = (size_t)(bh * HD + c) * PDIM + s1 * 1600;

    for (int e = t2; e < 1600; e += 128) {
        int r  = e / 40;
        int cc = e - r * 40;
        sQ[half][r][cc] = g_q[base + e];
        sK[half][r][cc] = g_k[base + e];
        sV[half][r][cc] = g_v[base + e];
    }
    __syncthreads();

    const float scale = 0.17677669529663687f;   // 32^-0.5
    const int i0 = (t2 / 10) * 4;
    const int j0 = (t2 % 10) * 4;

    float acc[4][4] = {};
    if (t2 < 100) {
        #pragma unroll 8
        for (int k = 0; k < 40; k++) {
            float qv[4], kv[4];
            #pragma unroll
            for (int a = 0; a < 4; a++) { qv[a] = sQ[half][i0 + a][k]; kv[a] = sK[half][j0 + a][k]; }
            #pragma unroll
            for (int a = 0; a < 4; a++)
                #pragma unroll
                for (int bb = 0; bb < 4; bb++)
                    acc[a][bb] = fmaf(qv[a], kv[bb], acc[a][bb]);
        }
    }
    __syncthreads();
    if (t2 < 100) {
        #pragma unroll
        for (int a = 0; a < 4; a++)
            #pragma unroll
            for (int bb = 0; bb < 4; bb++)
                sQ[half][i0 + a][j0 + bb] = acc[a][bb] * scale;
    }
    __syncthreads();

    if (t2 < 40) {
        float mx = -1e30f;
        #pragma unroll 8
        for (int j = 0; j < 40; j++) mx = fmaxf(mx, sQ[half][t2][j]);
        float sum = 0.0f;
        #pragma unroll 8
        for (int j = 0; j < 40; j++) {
            float ev = __expf(sQ[half][t2][j] - mx);
            sQ[half][t2][j] = ev;
            sum += ev;
        }
        const float inv = 1.0f / sum;
        #pragma unroll 8
        for (int j = 0; j < 40; j++) sQ[half][t2][j] *= inv;
    }
    __syncthreads();

    if (t2 < 100) {
        float acc2[4][4] = {};
        #pragma unroll 8
        for (int k = 0; k < 40; k++) {
            float av[4], vv[4];
            #pragma unroll
            for (int a = 0; a < 4; a++) { av[a] = sQ[half][i0 + a][k]; vv[a] = sV[half][k][j0 + a]; }
            #pragma unroll
            for (int a = 0; a < 4; a++)
                #pragma unroll
                for (int bb = 0; bb < 4; bb++)
                    acc2[a][bb] = fmaf(av[a], vv[bb], acc2[a][bb]);
        }
        #pragma unroll
        for (int a = 0; a < 4; a++) {
            float4 o = {3.0f * acc2[a][0], 3.0f * acc2[a][1],
                        3.0f * acc2[a][2], 3.0f * acc2[a][3]};
            *(float4*)&g_attn[base + (size_t)(i0 + a) * 40 + j0] = o;
        }
    }
}

// ---------------------------------------------------------------------------
extern "C" void kernel_launch(void* const* d_in, const int* in_sizes, int n_in,
                              void* d_out, int out_size)
{
    const float* x  = (const float*)d_in[0];
    const float* wq = (const float*)d_in[1];
    const float* bq = (const float*)d_in[2];
    const float* wk = (const float*)d_in[3];
    const float* bk = (const float*)d_in[4];
    const float* wv = (const float*)d_in[5];
    const float* bv = (const float*)d_in[6];
    const float* wp = (const float*)d_in[7];
    const float* bp = (const float*)d_in[8];
    float* out = (float*)d_out;

    convert_w<<<64, 256>>>(wq, wk, wv, wp);

    dim3 qkv_grid(PDIM / BN, 6, BATCH);              // 500 x 6 x 2
    qkv_gemm<<<qkv_grid, 128>>>(x, bq, bk, bv);

    dim3 attn_grid(SDIM, HD / 2, BATCH * HEADS);     // 40 x 16 x 16
    attn_kernel<<<attn_grid, 256>>>();

    dim3 proj_grid(PDIM / BN, 2, BATCH);             // 500 x 2 x 2
    proj_gemm<<<proj_grid, 128>>>(bp, out);
}